// round 3
// baseline (speedup 1.0000x reference)
#include <cuda_runtime.h>

// ShiftedConv2d_25872882991120 — R3
//
// Analytic collapse (bit-exact since R1): output is all zeros except
//   out[b, c*16+s, 0, 0] = tens[b,c,127,127] * filters[s,0,0,0]
// for each s with shifts[s] == (7,7).
//
// R2 post-mortem: occ 81% / issue 2.5% / time unchanged -> the generic
// SM store path is the wall (~1.74 TB/s useful), not thread geometry.
// R3: route the 64 MiB zero-fill through the driver memset engine
// (graph memset node, full-line write-only path), then patch the <=4096
// nonzero elements with a tiny kernel.

#define PLANES    4096          // B*C*S = 8*32*16
#define PLANE_F   16384         // 128*128 floats per plane

__global__ void shifted_conv_fixup_kernel(const float* __restrict__ tens,
                                          const float* __restrict__ filters,
                                          const int*   __restrict__ shifts,
                                          float* __restrict__ out)
{
    const unsigned plane = blockIdx.x * blockDim.x + threadIdx.x; // b*512+c*16+s
    if (plane >= PLANES) return;

    const unsigned s = plane & 15u;
    const int sh0 = shifts[2u * s];
    const int sh1 = shifts[2u * s + 1u];
    if (sh0 == 7 && sh1 == 7) {
        const unsigned c = (plane >> 4) & 31u;
        const unsigned b = plane >> 9;
        const unsigned n = b * 32u + c;
        out[(size_t)plane * PLANE_F] =
            tens[(n * 128u + 127u) * 128u + 127u] * filters[s * 49u];
    }
}

extern "C" void kernel_launch(void* const* d_in, const int* in_sizes, int n_in,
                              void* d_out, int out_size)
{
    const float* tens    = (const float*)d_in[0];
    const float* filters = (const float*)d_in[1];
    const int*   shifts  = (const int*)d_in[2];
    float*       out     = (float*)d_out;

    (void)in_sizes; (void)n_in;

    // 64 MiB write-only zero fill via the memset engine (graph memset node).
    cudaMemsetAsync(out, 0, (size_t)out_size * sizeof(float));

    // Patch the (at most 4096, typically ~a handful) nonzero outputs.
    shifted_conv_fixup_kernel<<<PLANES / 256, 256>>>(tens, filters, shifts, out);
}

// round 4
// speedup vs baseline: 1.0888x; 1.0888x over previous
#include <cuda_runtime.h>

// ShiftedConv2d_25872882991120 — R4
//
// Analytic collapse (bit-exact since R1): output is all zeros except
//   out[b, c*16+s, 0, 0] = tens[b,c,127,127] * filters[s,0,0,0]
// for each s with shifts[s] == (7,7).
//
// R3 post-mortem: output is 256 MiB (not 64 MiB as my comments claimed);
// R1 was already running at 7.14 TB/s = 89% of DRAM spec. This round:
// single kernel (no serial memset node), streaming stores (__stcs) so the
// 256 MiB one-shot write bypasses L2 allocation churn, 4 independent
// STG.128.CS per thread for store MLP. Roofline floor ~35-36 us kernel.

#define PLANES     4096                    // B * (C) * S = 8*32*16
#define PLANE_V4   4096                    // 128*128 floats / 4
#define OUT_V4     (PLANES * PLANE_V4)     // 16,777,216 float4 (256 MiB)
#define THREADS    256
#define V4_PER_THR 4

__global__ void __launch_bounds__(THREADS)
shifted_conv_fill_cs_kernel(const float* __restrict__ tens,
                            const float* __restrict__ filters,
                            const int*   __restrict__ shifts,
                            float4* __restrict__ out)
{
    // Each block owns a contiguous chunk of THREADS*V4_PER_THR = 1024 float4.
    const unsigned base = blockIdx.x * (THREADS * V4_PER_THR) + threadIdx.x;

    const float4 z = make_float4(0.f, 0.f, 0.f, 0.f);
    float4 v0 = z;

    // Plane heads sit at v4 indices that are multiples of PLANE_V4 (4096).
    // Chunk size 1024 divides 4096, so a head can only be the chunk's first
    // element: threadIdx.x == 0 and blockIdx.x % 4 == 0.
    if (threadIdx.x == 0 && (blockIdx.x & 3u) == 0u) {
        const unsigned plane = blockIdx.x >> 2;      // base / PLANE_V4
        const unsigned s = plane & 15u;
        const int sh0 = shifts[2u * s];
        const int sh1 = shifts[2u * s + 1u];
        if (sh0 == 7 && sh1 == 7) {
            const unsigned c = (plane >> 4) & 31u;
            const unsigned b = plane >> 9;
            const unsigned n = b * 32u + c;
            v0.x = tens[(n * 128u + 127u) * 128u + 127u] * filters[s * 49u];
        }
    }

    // 4 independent streaming STG.128 per thread; each warp iteration is a
    // contiguous 2 KB burst (full 128B lines).
    __stcs(out + base,               v0);
    __stcs(out + base + 1 * THREADS, z);
    __stcs(out + base + 2 * THREADS, z);
    __stcs(out + base + 3 * THREADS, z);
}

extern "C" void kernel_launch(void* const* d_in, const int* in_sizes, int n_in,
                              void* d_out, int out_size)
{
    const float* tens    = (const float*)d_in[0];
    const float* filters = (const float*)d_in[1];
    const int*   shifts  = (const int*)d_in[2];
    float4*      out     = (float4*)d_out;

    (void)in_sizes; (void)n_in; (void)out_size;

    // 16,777,216 v4 / (256 thr * 4 v4) = 16384 blocks, exact cover.
    shifted_conv_fill_cs_kernel<<<OUT_V4 / (THREADS * V4_PER_THR), THREADS>>>(
        tens, filters, shifts, out);
}